// round 12
// baseline (speedup 1.0000x reference)
#include <cuda_runtime.h>
#include <cuda_fp16.h>
#include <cstdint>

#define VOCAB 400000
#define DIM 300
#define KP 304                 // padded K (zeros 300..303), 38 x 16B chunks
#define NCH (KP / 8)           // 38 chunks of 8 halfs (16B)
#define NQ 512
#define TOPK 5
#define CAND 16
#define BN 64                  // vocab rows per tile
#define NTILES (VOCAB / BN)    // 6250
#define GRIDX 148
#define QGROUP 128
#define NQG (NQ / QGROUP)      // 4

#define PITCH 624              // smem row pitch bytes (39*16)
#define ABYTES (QGROUP * PITCH)        // 79872
#define BBYTES (BN * PITCH)            // 39936
#define DPITCH 65
#define DBYTES (QGROUP * DPITCH * 4)   // 33280
#define SMEM_BYTES (ABYTES + 2 * BBYTES + DBYTES)   // 193024

// ---------------- device scratch (no allocation allowed) -------------------
__device__ float g_invnorm[VOCAB];
__device__ __align__(128) __half g_Eh[(size_t)VOCAB * KP];   // 243 MB
__device__ __align__(128) __half g_Qh[NQ * KP];
__device__ float g_cv[(size_t)NQ * GRIDX * CAND];
__device__ int   g_ci[(size_t)NQ * GRIDX * CAND];

// ---------------- PTX helpers ----------------------------------------------
__device__ __forceinline__ uint32_t smem_u32(const void* p) {
    uint32_t a;
    asm("{ .reg .u64 t; cvta.to.shared.u64 t, %1; cvt.u32.u64 %0, t; }" : "=r"(a) : "l"(p));
    return a;
}
__device__ __forceinline__ void cpa16(uint32_t dst, const void* src) {
    asm volatile("cp.async.cg.shared.global [%0], [%1], 16;" :: "r"(dst), "l"(src) : "memory");
}
#define CP_COMMIT() asm volatile("cp.async.commit_group;" ::: "memory")
#define CP_WAIT(n)  asm volatile("cp.async.wait_group %0;" :: "n"(n) : "memory")

// ---------------- ordering helpers -----------------------------------------
__device__ __forceinline__ bool better(float av, int an, float bv, int bn) {
    return (av > bv) || (av == bv && an < bn);
}
__device__ __forceinline__ void ins16(float s, int n, float* v, int* nn) {
    if (better(s, n, v[CAND - 1], nn[CAND - 1])) {
        v[CAND - 1] = s; nn[CAND - 1] = n;
        #pragma unroll
        for (int j = CAND - 1; j > 0; j--) {
            if (better(v[j], nn[j], v[j - 1], nn[j - 1])) {
                float tv = v[j]; v[j] = v[j - 1]; v[j - 1] = tv;
                int tn = nn[j]; nn[j] = nn[j - 1]; nn[j - 1] = tn;
            }
        }
    }
}
__device__ __forceinline__ void merge16(float* v, int* nn, const float* ov, const int* on) {
    float rv[CAND]; int rn[CAND]; int a = 0, b = 0;
    #pragma unroll
    for (int j = 0; j < CAND; j++) {
        bool ta = better(v[a], nn[a], ov[b], on[b]);
        rv[j] = ta ? v[a] : ov[b];
        rn[j] = ta ? nn[a] : on[b];
        if (ta) a++; else b++;
    }
    #pragma unroll
    for (int j = 0; j < CAND; j++) { v[j] = rv[j]; nn[j] = rn[j]; }
}

// ---------------------------------------------------------------------------
// Kernel 1: per-row invnorm -> fp16 normalized table (zero-padded to KP)
// ---------------------------------------------------------------------------
__global__ void prep_kernel(const float* __restrict__ E) {
    int row = blockIdx.x * (blockDim.x >> 5) + (threadIdx.x >> 5);
    int lane = threadIdx.x & 31;
    if (row >= VOCAB) return;
    const float4* r4 = (const float4*)(E + (size_t)row * DIM);
    float s = 0.f;
    for (int i = lane; i < DIM / 4; i += 32) {
        float4 v = r4[i];
        s += v.x * v.x + v.y * v.y + v.z * v.z + v.w * v.w;
    }
    #pragma unroll
    for (int off = 16; off; off >>= 1) s += __shfl_xor_sync(0xffffffffu, s, off);
    float inv = 1.0f / sqrtf(s);
    if (lane == 0) g_invnorm[row] = inv;
    const float* src = E + (size_t)row * DIM;
    __half2* dst = (__half2*)(g_Eh + (size_t)row * KP);
    for (int j = lane; j < KP / 2; j += 32) {
        int k = 2 * j;
        float a = (k < DIM) ? src[k] * inv : 0.f;
        float b = (k + 1 < DIM) ? src[k + 1] * inv : 0.f;
        dst[j] = __floats2half2_rn(a, b);
    }
}

// ---------------------------------------------------------------------------
// Kernel 2: gather queries -> fp16 normalized, padded
// ---------------------------------------------------------------------------
__global__ void gatherq_kernel(const float* __restrict__ E, const int* __restrict__ ids) {
    int q = blockIdx.x * (blockDim.x >> 5) + (threadIdx.x >> 5);
    int lane = threadIdx.x & 31;
    if (q >= NQ) return;
    int id = ids[q];
    float inv = g_invnorm[id];
    const float* src = E + (size_t)id * DIM;
    __half2* dst = (__half2*)(g_Qh + (size_t)q * KP);
    for (int j = lane; j < KP / 2; j += 32) {
        int k = 2 * j;
        float a = (k < DIM) ? src[k] * inv : 0.f;
        float b = (k + 1 < DIM) ? src[k + 1] * inv : 0.f;
        dst[j] = __floats2half2_rn(a, b);
    }
}

// ---------------------------------------------------------------------------
// Kernel 3: HFMA2 GEMM (128 queries x 64 vocab x K=304) + per-query top-16
// 256 threads: tx = tid&15 (cols tx+16j, j<4), ty = tid>>4 (rows ty+16i, i<8)
// half2 accumulators: lo/hi hold even/odd-k partial sums.
// ---------------------------------------------------------------------------
__global__ __launch_bounds__(256, 1) void gemm_topk_kernel() {
    extern __shared__ __align__(16) char smem[];
    char* A_S = smem;
    char* B_S = smem + ABYTES;
    float* Ds = (float*)(smem + ABYTES + 2 * BBYTES);

    const int tid = threadIdx.x;
    const int tx = tid & 15;
    const int ty = tid >> 4;
    const int qg = blockIdx.x;
    const int bx = blockIdx.y;
    const int nt = (NTILES - bx + GRIDX - 1) / GRIDX;

    // A load (queries, resident) + first B tile
    const __half* Qsrc = g_Qh + (size_t)qg * QGROUP * KP;
    for (int i = tid; i < QGROUP * NCH; i += 256)
        cpa16(smem_u32(A_S + (i / NCH) * PITCH + (i % NCH) * 16),
              Qsrc + (size_t)(i / NCH) * KP + (i % NCH) * 8);
    {
        const __half* src = g_Eh + (size_t)bx * BN * KP;
        for (int i = tid; i < BN * NCH; i += 256)
            cpa16(smem_u32(B_S + (i / NCH) * PITCH + (i % NCH) * 16),
                  src + (size_t)(i / NCH) * KP + (i % NCH) * 8);
    }
    CP_COMMIT();

    float cv[CAND]; int ci[CAND];
    #pragma unroll
    for (int j = 0; j < CAND; j++) { cv[j] = -1e30f; ci[j] = 0x7fffffff; }

    for (int t = 0; t < nt; t++) {
        if (t + 1 < nt) {
            int vt = bx + (t + 1) * GRIDX;
            char* base = B_S + ((t + 1) & 1) * BBYTES;
            const __half* src = g_Eh + (size_t)vt * BN * KP;
            for (int i = tid; i < BN * NCH; i += 256)
                cpa16(smem_u32(base + (i / NCH) * PITCH + (i % NCH) * 16),
                      src + (size_t)(i / NCH) * KP + (i % NCH) * 8);
            CP_COMMIT();
            CP_WAIT(1);
        } else {
            CP_WAIT(0);
        }
        __syncthreads();

        const char* Bb = B_S + (t & 1) * BBYTES;
        __half2 acc[8][4];
        #pragma unroll
        for (int i = 0; i < 8; i++)
            #pragma unroll
            for (int j = 0; j < 4; j++) acc[i][j] = __float2half2_rn(0.f);

        #pragma unroll 2
        for (int c = 0; c < NCH; c++) {
            int4 bfr[4];
            #pragma unroll
            for (int j = 0; j < 4; j++)
                bfr[j] = *(const int4*)(Bb + (tx + 16 * j) * PITCH + c * 16);
            const __half2* bh0 = (const __half2*)&bfr[0];
            const __half2* bh1 = (const __half2*)&bfr[1];
            const __half2* bh2 = (const __half2*)&bfr[2];
            const __half2* bh3 = (const __half2*)&bfr[3];
            #pragma unroll
            for (int i = 0; i < 8; i++) {
                int4 afr = *(const int4*)(A_S + (ty + 16 * i) * PITCH + c * 16);
                const __half2* ah = (const __half2*)&afr;
                #pragma unroll
                for (int tkt = 0; tkt < 4; tkt++) {
                    acc[i][0] = __hfma2(ah[tkt], bh0[tkt], acc[i][0]);
                    acc[i][1] = __hfma2(ah[tkt], bh1[tkt], acc[i][1]);
                    acc[i][2] = __hfma2(ah[tkt], bh2[tkt], acc[i][2]);
                    acc[i][3] = __hfma2(ah[tkt], bh3[tkt], acc[i][3]);
                }
            }
        }

        // stage D (fp32 = lo+hi) to smem
        #pragma unroll
        for (int i = 0; i < 8; i++) {
            int r = ty + 16 * i;
            #pragma unroll
            for (int j = 0; j < 4; j++)
                Ds[r * DPITCH + tx + 16 * j] = __low2float(acc[i][j]) + __high2float(acc[i][j]);
        }
        __syncthreads();

        // per-query top-16 scan (1 thread per query row)
        if (tid < QGROUP) {
            const float* row = Ds + tid * DPITCH;
            int vbase = (bx + t * GRIDX) * BN;
            #pragma unroll 8
            for (int cc = 0; cc < BN; cc++) ins16(row[cc], vbase + cc, cv, ci);
        }
        __syncthreads();
    }

    if (tid < QGROUP) {
        int q = qg * QGROUP + tid;
        size_t base = ((size_t)q * GRIDX + bx) * CAND;
        #pragma unroll
        for (int j = 0; j < CAND; j++) { g_cv[base + j] = cv[j]; g_ci[base + j] = ci[j]; }
    }
}

// ---------------------------------------------------------------------------
// Kernel 4: global approx top-16 -> exact fp32 rescore -> top-5 out
// ---------------------------------------------------------------------------
__global__ void final_kernel(const float* __restrict__ E, const int* __restrict__ ids,
                             float* __restrict__ out) {
    __shared__ float sv[256][CAND];
    __shared__ int   sn[256][CAND];
    __shared__ float ev[CAND];
    int q = blockIdx.x, tid = threadIdx.x;

    float v[CAND]; int nn[CAND];
    #pragma unroll
    for (int j = 0; j < CAND; j++) { v[j] = -1e30f; nn[j] = 0x7fffffff; }
    size_t base = (size_t)q * GRIDX * CAND;
    for (int i = tid; i < GRIDX * CAND; i += 256) ins16(g_cv[base + i], g_ci[base + i], v, nn);
    #pragma unroll
    for (int j = 0; j < CAND; j++) { sv[tid][j] = v[j]; sn[tid][j] = nn[j]; }
    __syncthreads();
    for (int s = 128; s > 0; s >>= 1) {
        if (tid < s) {
            float ov[CAND]; int on[CAND];
            #pragma unroll
            for (int j = 0; j < CAND; j++) {
                v[j] = sv[tid][j]; nn[j] = sn[tid][j];
                ov[j] = sv[tid + s][j]; on[j] = sn[tid + s][j];
            }
            merge16(v, nn, ov, on);
            #pragma unroll
            for (int j = 0; j < CAND; j++) { sv[tid][j] = v[j]; sn[tid][j] = nn[j]; }
        }
        __syncthreads();
    }
    // exact fp32 rescore of the 16 surviving candidates
    int wid = tid >> 5, lane = tid & 31;
    int qid = ids[q];
    float invq = g_invnorm[qid];
    for (int c = wid; c < CAND; c += 8) {
        int vi = sn[0][c];
        float val = -1e30f;
        if (vi >= 0 && vi < VOCAB) {
            const float* a = E + (size_t)qid * DIM;
            const float* b = E + (size_t)vi * DIM;
            float s = 0.f;
            for (int k = lane; k < DIM; k += 32) s += a[k] * b[k];
            #pragma unroll
            for (int off = 16; off; off >>= 1) s += __shfl_xor_sync(0xffffffffu, s, off);
            val = s * invq * g_invnorm[vi];
        }
        if (lane == 0) ev[c] = val;
    }
    __syncthreads();
    if (tid == 0) {
        bool used[CAND];
        #pragma unroll
        for (int j = 0; j < CAND; j++) used[j] = false;
        for (int j = 0; j < TOPK; j++) {
            int best = -1;
            for (int c = 0; c < CAND; c++) {
                if (used[c]) continue;
                if (best < 0 || better(ev[c], sn[0][c], ev[best], sn[0][best])) best = c;
            }
            used[best] = true;
            out[q * TOPK + j] = ev[best];
            out[NQ * TOPK + q * TOPK + j] = (float)sn[0][best];
        }
    }
}

// ---------------------------------------------------------------------------
extern "C" void kernel_launch(void* const* d_in, const int* in_sizes, int n_in,
                              void* d_out, int out_size) {
    const float* E = (const float*)d_in[0];
    const int* ids = (const int*)d_in[1];
    float* out = (float*)d_out;

    cudaFuncSetAttribute(gemm_topk_kernel, cudaFuncAttributeMaxDynamicSharedMemorySize, SMEM_BYTES);

    prep_kernel<<<VOCAB / 8, 256>>>(E);
    gatherq_kernel<<<NQ / 8, 256>>>(E, ids);
    gemm_topk_kernel<<<dim3(NQG, GRIDX), 256, SMEM_BYTES>>>();
    final_kernel<<<NQ, 256>>>(E, ids, out);
}

// round 13
// speedup vs baseline: 1.3567x; 1.3567x over previous
#include <cuda_runtime.h>
#include <cuda_bf16.h>
#include <cstdint>

#define VOCAB 400000
#define DIM 300
#define KP 304                 // padded K (zeros 300..303), 19 k16-steps
#define NCH (KP / 8)           // 38 x 16B chunks per row
#define KSTEPS (KP / 16)       // 19
#define NQ 512
#define TOPK 5
#define CAND 16
#define BN 64
#define NTILES (VOCAB / BN)    // 6250
#define GRIDX 148
#define QGROUP 128
#define NQG (NQ / QGROUP)      // 4

#define PITCH 624              // bytes (39*16) - conflict-free ldmatrix
#define ABYTES (QGROUP * PITCH)        // 79872
#define BBYTES (BN * PITCH)            // 39936
#define DPITCH 66
#define DBYTES (QGROUP * DPITCH * 4)   // 33792
#define SMEM_BYTES (ABYTES + 2 * BBYTES + DBYTES)   // 193536

// ---------------- device scratch -------------------------------------------
__device__ float g_invnorm[VOCAB];
__device__ __align__(128) __nv_bfloat16 g_Ebf[(size_t)VOCAB * KP];   // 243 MB
__device__ __align__(128) __nv_bfloat16 g_Qbf[NQ * KP];
__device__ float g_cv[(size_t)NQ * GRIDX * CAND];
__device__ int   g_ci[(size_t)NQ * GRIDX * CAND];

// ---------------- PTX helpers ----------------------------------------------
__device__ __forceinline__ uint32_t smem_u32(const void* p) {
    uint32_t a;
    asm("{ .reg .u64 t; cvta.to.shared.u64 t, %1; cvt.u32.u64 %0, t; }" : "=r"(a) : "l"(p));
    return a;
}
__device__ __forceinline__ void cpa16(uint32_t dst, const void* src) {
    asm volatile("cp.async.cg.shared.global [%0], [%1], 16;" :: "r"(dst), "l"(src) : "memory");
}
#define CP_COMMIT() asm volatile("cp.async.commit_group;" ::: "memory")
#define CP_WAIT(n)  asm volatile("cp.async.wait_group %0;" :: "n"(n) : "memory")

__device__ __forceinline__ void ldsm_x4(uint32_t* r, uint32_t addr) {
    asm volatile("ldmatrix.sync.aligned.m8n8.x4.shared.b16 {%0,%1,%2,%3}, [%4];"
                 : "=r"(r[0]), "=r"(r[1]), "=r"(r[2]), "=r"(r[3]) : "r"(addr));
}
__device__ __forceinline__ void mma_bf16(float* d, const uint32_t* a, uint32_t b0, uint32_t b1) {
    asm volatile("mma.sync.aligned.m16n8k16.row.col.f32.bf16.bf16.f32 "
                 "{%0,%1,%2,%3}, {%4,%5,%6,%7}, {%8,%9}, {%0,%1,%2,%3};"
                 : "+f"(d[0]), "+f"(d[1]), "+f"(d[2]), "+f"(d[3])
                 : "r"(a[0]), "r"(a[1]), "r"(a[2]), "r"(a[3]), "r"(b0), "r"(b1));
}

// ---------------- ordering helpers -----------------------------------------
__device__ __forceinline__ bool better(float av, int an, float bv, int bn) {
    return (av > bv) || (av == bv && an < bn);
}
__device__ __forceinline__ void ins16(float s, int n, float* v, int* nn) {
    if (better(s, n, v[CAND - 1], nn[CAND - 1])) {
        v[CAND - 1] = s; nn[CAND - 1] = n;
        #pragma unroll
        for (int j = CAND - 1; j > 0; j--) {
            if (better(v[j], nn[j], v[j - 1], nn[j - 1])) {
                float tv = v[j]; v[j] = v[j - 1]; v[j - 1] = tv;
                int tn = nn[j]; nn[j] = nn[j - 1]; nn[j - 1] = tn;
            }
        }
    }
}
__device__ __forceinline__ void merge16(float* v, int* nn, const float* ov, const int* on) {
    float rv[CAND]; int rn[CAND]; int a = 0, b = 0;
    #pragma unroll
    for (int j = 0; j < CAND; j++) {
        bool ta = better(v[a], nn[a], ov[b], on[b]);
        rv[j] = ta ? v[a] : ov[b];
        rn[j] = ta ? nn[a] : on[b];
        if (ta) a++; else b++;
    }
    #pragma unroll
    for (int j = 0; j < CAND; j++) { v[j] = rv[j]; nn[j] = rn[j]; }
}

// ---------------------------------------------------------------------------
// no-op kernel: pads the launch sequence so ncu (-s 5 -c 1) profiles the GEMM
// ---------------------------------------------------------------------------
__global__ void noop_kernel() {}

// ---------------------------------------------------------------------------
// Kernel 1: per-row invnorm -> bf16 normalized table (zero-padded to KP)
// ---------------------------------------------------------------------------
__global__ void prep_kernel(const float* __restrict__ E) {
    int row = blockIdx.x * (blockDim.x >> 5) + (threadIdx.x >> 5);
    int lane = threadIdx.x & 31;
    if (row >= VOCAB) return;
    const float4* r4 = (const float4*)(E + (size_t)row * DIM);
    float s = 0.f;
    for (int i = lane; i < DIM / 4; i += 32) {
        float4 v = r4[i];
        s += v.x * v.x + v.y * v.y + v.z * v.z + v.w * v.w;
    }
    #pragma unroll
    for (int off = 16; off; off >>= 1) s += __shfl_xor_sync(0xffffffffu, s, off);
    float inv = 1.0f / sqrtf(s);
    if (lane == 0) g_invnorm[row] = inv;
    const float* src = E + (size_t)row * DIM;
    __nv_bfloat162* dst = (__nv_bfloat162*)(g_Ebf + (size_t)row * KP);
    for (int j = lane; j < KP / 2; j += 32) {
        int k = 2 * j;
        float a = (k < DIM) ? src[k] * inv : 0.f;
        float b = (k + 1 < DIM) ? src[k + 1] * inv : 0.f;
        dst[j] = __floats2bfloat162_rn(a, b);
    }
}

// ---------------------------------------------------------------------------
// Kernel 2: gather queries -> bf16 normalized, padded
// ---------------------------------------------------------------------------
__global__ void gatherq_kernel(const float* __restrict__ E, const int* __restrict__ ids) {
    int q = blockIdx.x * (blockDim.x >> 5) + (threadIdx.x >> 5);
    int lane = threadIdx.x & 31;
    if (q >= NQ) return;
    int id = ids[q];
    float inv = g_invnorm[id];
    const float* src = E + (size_t)id * DIM;
    __nv_bfloat162* dst = (__nv_bfloat162*)(g_Qbf + (size_t)q * KP);
    for (int j = lane; j < KP / 2; j += 32) {
        int k = 2 * j;
        float a = (k < DIM) ? src[k] * inv : 0.f;
        float b = (k + 1 < DIM) ? src[k + 1] * inv : 0.f;
        dst[j] = __floats2bfloat162_rn(a, b);
    }
}

// ---------------------------------------------------------------------------
// Kernel 3: bf16 mma.sync GEMM (128q x 64v x K=304) + top-16
// 8 warps (4 M x 2 N), warp tile 32x32, double-buffered fragments.
// ---------------------------------------------------------------------------
__global__ __launch_bounds__(256, 1) void gemm_topk_kernel() {
    extern __shared__ __align__(16) char smem[];
    const uint32_t A_S = smem_u32(smem);
    const uint32_t B_S = A_S + ABYTES;
    float* Ds = (float*)(smem + ABYTES + 2 * BBYTES);

    const int tid = threadIdx.x;
    const int lane = tid & 31;
    const int wid = tid >> 5;
    const int wm = wid & 3;
    const int wn = wid >> 2;
    const int qg = blockIdx.x;
    const int bx = blockIdx.y;
    const int nt = (NTILES - bx + GRIDX - 1) / GRIDX;

    // A (resident) + first B tile
    const __nv_bfloat16* Qsrc = g_Qbf + (size_t)qg * QGROUP * KP;
    for (int i = tid; i < QGROUP * NCH; i += 256)
        cpa16(A_S + (i / NCH) * PITCH + (i % NCH) * 16, Qsrc + (size_t)(i / NCH) * KP + (i % NCH) * 8);
    {
        const __nv_bfloat16* src = g_Ebf + (size_t)bx * BN * KP;
        for (int i = tid; i < BN * NCH; i += 256)
            cpa16(B_S + (i / NCH) * PITCH + (i % NCH) * 16, src + (size_t)(i / NCH) * KP + (i % NCH) * 8);
    }
    CP_COMMIT();

    uint32_t a_off[2], b_off[2];
    #pragma unroll
    for (int mt = 0; mt < 2; mt++) {
        int r = wm * 32 + mt * 16 + (lane & 7) + ((lane >> 3) & 1) * 8;
        a_off[mt] = A_S + (uint32_t)r * PITCH + (uint32_t)(lane >> 4) * 16;
    }
    #pragma unroll
    for (int np = 0; np < 2; np++) {
        int r = wn * 32 + np * 16 + (lane & 7) + (lane >> 4) * 8;
        b_off[np] = (uint32_t)r * PITCH + (uint32_t)((lane >> 3) & 1) * 16;
    }

    float cv[CAND]; int ci[CAND];
    #pragma unroll
    for (int j = 0; j < CAND; j++) { cv[j] = -1e30f; ci[j] = 0x7fffffff; }

    for (int t = 0; t < nt; t++) {
        if (t + 1 < nt) {
            int vt = bx + (t + 1) * GRIDX;
            uint32_t base = B_S + (uint32_t)((t + 1) & 1) * BBYTES;
            const __nv_bfloat16* src = g_Ebf + (size_t)vt * BN * KP;
            for (int i = tid; i < BN * NCH; i += 256)
                cpa16(base + (i / NCH) * PITCH + (i % NCH) * 16, src + (size_t)(i / NCH) * KP + (i % NCH) * 8);
            CP_COMMIT();
            CP_WAIT(1);
        } else {
            CP_WAIT(0);
        }
        __syncthreads();

        const uint32_t Bb = B_S + (uint32_t)(t & 1) * BBYTES;
        float d[2][4][4];
        #pragma unroll
        for (int mt = 0; mt < 2; mt++)
            #pragma unroll
            for (int n = 0; n < 4; n++)
                #pragma unroll
                for (int j = 0; j < 4; j++) d[mt][n][j] = 0.f;

        // double-buffered fragments over 19 k-steps (32 bytes per step)
        uint32_t a[2][2][4], b[2][2][4];
        ldsm_x4(a[0][0], a_off[0]);
        ldsm_x4(a[0][1], a_off[1]);
        ldsm_x4(b[0][0], Bb + b_off[0]);
        ldsm_x4(b[0][1], Bb + b_off[1]);

        #pragma unroll
        for (int ks = 0; ks < KSTEPS; ks++) {
            const int cur = ks & 1, nxt = cur ^ 1;
            if (ks + 1 < KSTEPS) {
                uint32_t off = (uint32_t)(ks + 1) * 32u;
                ldsm_x4(a[nxt][0], a_off[0] + off);
                ldsm_x4(a[nxt][1], a_off[1] + off);
                ldsm_x4(b[nxt][0], Bb + b_off[0] + off);
                ldsm_x4(b[nxt][1], Bb + b_off[1] + off);
            }
            #pragma unroll
            for (int mt = 0; mt < 2; mt++) {
                mma_bf16(d[mt][0], a[cur][mt], b[cur][0][0], b[cur][0][1]);
                mma_bf16(d[mt][1], a[cur][mt], b[cur][0][2], b[cur][0][3]);
                mma_bf16(d[mt][2], a[cur][mt], b[cur][1][0], b[cur][1][1]);
                mma_bf16(d[mt][3], a[cur][mt], b[cur][1][2], b[cur][1][3]);
            }
        }

        // stage D to smem
        #pragma unroll
        for (int mt = 0; mt < 2; mt++) {
            int r0 = wm * 32 + mt * 16 + (lane >> 2);
            #pragma unroll
            for (int n = 0; n < 4; n++) {
                int c0 = wn * 32 + n * 8 + (lane & 3) * 2;
                *(float2*)&Ds[r0 * DPITCH + c0]       = make_float2(d[mt][n][0], d[mt][n][1]);
                *(float2*)&Ds[(r0 + 8) * DPITCH + c0] = make_float2(d[mt][n][2], d[mt][n][3]);
            }
        }
        __syncthreads();

        if (tid < QGROUP) {
            const float* row = Ds + tid * DPITCH;
            int vbase = (bx + t * GRIDX) * BN;
            #pragma unroll 8
            for (int c = 0; c < BN; c++) ins16(row[c], vbase + c, cv, ci);
        }
        __syncthreads();
    }

    if (tid < QGROUP) {
        int q = qg * QGROUP + tid;
        size_t base = ((size_t)q * GRIDX + bx) * CAND;
        #pragma unroll
        for (int j = 0; j < CAND; j++) { g_cv[base + j] = cv[j]; g_ci[base + j] = ci[j]; }
    }
}

// ---------------------------------------------------------------------------
// Kernel 4: global approx top-16 -> exact fp32 rescore -> top-5 out
// ---------------------------------------------------------------------------
__global__ void final_kernel(const float* __restrict__ E, const int* __restrict__ ids,
                             float* __restrict__ out) {
    __shared__ float sv[256][CAND];
    __shared__ int   sn[256][CAND];
    __shared__ float ev[CAND];
    int q = blockIdx.x, tid = threadIdx.x;

    float v[CAND]; int nn[CAND];
    #pragma unroll
    for (int j = 0; j < CAND; j++) { v[j] = -1e30f; nn[j] = 0x7fffffff; }
    size_t base = (size_t)q * GRIDX * CAND;
    for (int i = tid; i < GRIDX * CAND; i += 256) ins16(g_cv[base + i], g_ci[base + i], v, nn);
    #pragma unroll
    for (int j = 0; j < CAND; j++) { sv[tid][j] = v[j]; sn[tid][j] = nn[j]; }
    __syncthreads();
    for (int s = 128; s > 0; s >>= 1) {
        if (tid < s) {
            float ov[CAND]; int on[CAND];
            #pragma unroll
            for (int j = 0; j < CAND; j++) {
                v[j] = sv[tid][j]; nn[j] = sn[tid][j];
                ov[j] = sv[tid + s][j]; on[j] = sn[tid + s][j];
            }
            merge16(v, nn, ov, on);
            #pragma unroll
            for (int j = 0; j < CAND; j++) { sv[tid][j] = v[j]; sn[tid][j] = nn[j]; }
        }
        __syncthreads();
    }
    int wid = tid >> 5, lane = tid & 31;
    int qid = ids[q];
    float invq = g_invnorm[qid];
    for (int c = wid; c < CAND; c += 8) {
        int vi = sn[0][c];
        float val = -1e30f;
        if (vi >= 0 && vi < VOCAB) {
            const float* a = E + (size_t)qid * DIM;
            const float* b = E + (size_t)vi * DIM;
            float s = 0.f;
            for (int k = lane; k < DIM; k += 32) s += a[k] * b[k];
            #pragma unroll
            for (int off = 16; off; off >>= 1) s += __shfl_xor_sync(0xffffffffu, s, off);
            val = s * invq * g_invnorm[vi];
        }
        if (lane == 0) ev[c] = val;
    }
    __syncthreads();
    if (tid == 0) {
        bool used[CAND];
        #pragma unroll
        for (int j = 0; j < CAND; j++) used[j] = false;
        for (int j = 0; j < TOPK; j++) {
            int best = -1;
            for (int c = 0; c < CAND; c++) {
                if (used[c]) continue;
                if (best < 0 || better(ev[c], sn[0][c], ev[best], sn[0][best])) best = c;
            }
            used[best] = true;
            out[q * TOPK + j] = ev[best];
            out[NQ * TOPK + q * TOPK + j] = (float)sn[0][best];
        }
    }
}

// ---------------------------------------------------------------------------
extern "C" void kernel_launch(void* const* d_in, const int* in_sizes, int n_in,
                              void* d_out, int out_size) {
    const float* E = (const float*)d_in[0];
    const int* ids = (const int*)d_in[1];
    float* out = (float*)d_out;

    cudaFuncSetAttribute(gemm_topk_kernel, cudaFuncAttributeMaxDynamicSharedMemorySize, SMEM_BYTES);

    prep_kernel<<<VOCAB / 8, 256>>>(E);          // launch 1
    gatherq_kernel<<<NQ / 8, 256>>>(E, ids);     // launch 2
    noop_kernel<<<1, 32>>>();                    // launch 3
    noop_kernel<<<1, 32>>>();                    // launch 4
    noop_kernel<<<1, 32>>>();                    // launch 5
    gemm_topk_kernel<<<dim3(NQG, GRIDX), 256, SMEM_BYTES>>>();  // launch 6 <- ncu lands here
    final_kernel<<<NQ, 256>>>(E, ids, out);      // launch 7
}

// round 15
// speedup vs baseline: 1.4418x; 1.0628x over previous
#include <cuda_runtime.h>
#include <cuda_bf16.h>
#include <cstdint>

#define VOCAB 400000
#define DIM 300
#define KP 304                 // padded K (zeros 300..303), 19 k16-steps
#define NCH (KP / 8)           // 38 x 16B chunks per row
#define NQ 512
#define TOPK 5
#define CAND 16
#define BN 64                  // vocab rows per tile
#define NTILES (VOCAB / BN)    // 6250
#define GRIDX 148
#define QGROUP 128
#define NQG (NQ / QGROUP)      // 4

#define APITCH 312             // smem pitch in bf16 elems (624B = 39*16, conflict-free)
#define ABYTES (QGROUP * APITCH * 2)   // 79872
#define BBYTES (BN * APITCH * 2)       // 39936
#define DPITCH 66
#define DBYTES (QGROUP * DPITCH * 4)   // 33792
#define SMEM_BYTES (1024 + ABYTES + 2 * BBYTES + DBYTES)

// ---------------- device scratch (no allocation allowed) -------------------
__device__ float g_invnorm[VOCAB];
__device__ __align__(128) __nv_bfloat16 g_Ebf[(size_t)VOCAB * KP];   // 243 MB
__device__ __align__(128) __nv_bfloat16 g_Qbf[NQ * KP];
__device__ float g_cv[(size_t)NQ * GRIDX * CAND];
__device__ int   g_ci[(size_t)NQ * GRIDX * CAND];

// ---------------- PTX helpers ----------------------------------------------
__device__ __forceinline__ uint32_t smem_u32(const void* p) {
    uint32_t a;
    asm("{ .reg .u64 t; cvta.to.shared.u64 t, %1; cvt.u32.u64 %0, t; }" : "=r"(a) : "l"(p));
    return a;
}
__device__ __forceinline__ void cpa16(uint32_t dst, const void* src) {
    asm volatile("cp.async.cg.shared.global [%0], [%1], 16;" :: "r"(dst), "l"(src) : "memory");
}
#define CP_COMMIT() asm volatile("cp.async.commit_group;" ::: "memory")
#define CP_WAIT(n)  asm volatile("cp.async.wait_group %0;" :: "n"(n) : "memory")

__device__ __forceinline__ void ldsm_x4(uint32_t* r, uint32_t addr) {
    asm volatile("ldmatrix.sync.aligned.m8n8.x4.shared.b16 {%0,%1,%2,%3}, [%4];"
                 : "=r"(r[0]), "=r"(r[1]), "=r"(r[2]), "=r"(r[3]) : "r"(addr));
}
__device__ __forceinline__ void mma_bf16(float* d, const uint32_t* a, uint32_t b0, uint32_t b1) {
    asm volatile("mma.sync.aligned.m16n8k16.row.col.f32.bf16.bf16.f32 "
                 "{%0,%1,%2,%3}, {%4,%5,%6,%7}, {%8,%9}, {%0,%1,%2,%3};"
                 : "+f"(d[0]), "+f"(d[1]), "+f"(d[2]), "+f"(d[3])
                 : "r"(a[0]), "r"(a[1]), "r"(a[2]), "r"(a[3]), "r"(b0), "r"(b1));
}

// ---------------- ordering helpers -----------------------------------------
__device__ __forceinline__ bool better(float av, int an, float bv, int bn) {
    return (av > bv) || (av == bv && an < bn);
}
__device__ __forceinline__ void ins16(float s, int n, float* v, int* nn) {
    if (better(s, n, v[CAND - 1], nn[CAND - 1])) {
        v[CAND - 1] = s; nn[CAND - 1] = n;
        #pragma unroll
        for (int j = CAND - 1; j > 0; j--) {
            if (better(v[j], nn[j], v[j - 1], nn[j - 1])) {
                float tv = v[j]; v[j] = v[j - 1]; v[j - 1] = tv;
                int tn = nn[j]; nn[j] = nn[j - 1]; nn[j - 1] = tn;
            }
        }
    }
}
__device__ __forceinline__ void merge16(float* v, int* nn, const float* ov, const int* on) {
    float rv[CAND]; int rn[CAND]; int a = 0, b = 0;
    #pragma unroll
    for (int j = 0; j < CAND; j++) {
        bool ta = better(v[a], nn[a], ov[b], on[b]);
        rv[j] = ta ? v[a] : ov[b];
        rn[j] = ta ? nn[a] : on[b];
        if (ta) a++; else b++;
    }
    #pragma unroll
    for (int j = 0; j < CAND; j++) { v[j] = rv[j]; nn[j] = rn[j]; }
}

// ---------------------------------------------------------------------------
// Kernel 1: per-row invnorm -> bf16 normalized table (KP = 304, zeros at end)
// ---------------------------------------------------------------------------
__global__ void prep_kernel(const float* __restrict__ E) {
    int row = blockIdx.x * (blockDim.x >> 5) + (threadIdx.x >> 5);
    int lane = threadIdx.x & 31;
    if (row >= VOCAB) return;
    const float4* r4 = (const float4*)(E + (size_t)row * DIM);
    float s = 0.f;
    for (int i = lane; i < DIM / 4; i += 32) {
        float4 v = r4[i];
        s += v.x * v.x + v.y * v.y + v.z * v.z + v.w * v.w;
    }
    #pragma unroll
    for (int off = 16; off; off >>= 1) s += __shfl_xor_sync(0xffffffffu, s, off);
    float inv = 1.0f / sqrtf(s);
    if (lane == 0) g_invnorm[row] = inv;
    const float* src = E + (size_t)row * DIM;
    __nv_bfloat162* dst = (__nv_bfloat162*)(g_Ebf + (size_t)row * KP);
    for (int j = lane; j < KP / 2; j += 32) {
        int k = 2 * j;
        float a = (k < DIM) ? src[k] * inv : 0.f;
        float b = (k + 1 < DIM) ? src[k + 1] * inv : 0.f;
        dst[j] = __floats2bfloat162_rn(a, b);
    }
}

// ---------------------------------------------------------------------------
// Kernel 2: gather queries -> bf16 normalized, padded
// ---------------------------------------------------------------------------
__global__ void gatherq_kernel(const float* __restrict__ E, const int* __restrict__ ids) {
    int q = blockIdx.x * (blockDim.x >> 5) + (threadIdx.x >> 5);
    int lane = threadIdx.x & 31;
    if (q >= NQ) return;
    int id = ids[q];
    float inv = g_invnorm[id];
    const float* src = E + (size_t)id * DIM;
    __nv_bfloat162* dst = (__nv_bfloat162*)(g_Qbf + (size_t)q * KP);
    for (int j = lane; j < KP / 2; j += 32) {
        int k = 2 * j;
        float a = (k < DIM) ? src[k] * inv : 0.f;
        float b = (k + 1 < DIM) ? src[k + 1] * inv : 0.f;
        dst[j] = __floats2bfloat162_rn(a, b);
    }
}

// ---------------------------------------------------------------------------
// Kernel 3: bf16 mma.sync GEMM (128 queries x 64 vocab x K=304) + top-16
// 256 threads = 8 warps (4 in M x 2 in N). Warp tile 32x32.  (R6 structure)
// ---------------------------------------------------------------------------
__global__ __launch_bounds__(256, 1) void gemm_topk_kernel() {
    extern __shared__ char smem[];
    uint32_t sb = smem_u32(smem);
    uint32_t ab = (sb + 1023u) & ~1023u;
    const uint32_t A_S = ab;
    const uint32_t B_S = ab + ABYTES;
    float* Ds = (float*)(smem + (ab - sb) + ABYTES + 2 * BBYTES);

    const int tid = threadIdx.x;
    const int lane = tid & 31;
    const int wid = tid >> 5;
    const int wm = wid & 3;          // 0..3 -> M
    const int wn = wid >> 2;         // 0..1 -> N
    const int qg = blockIdx.x;
    const int bx = blockIdx.y;
    const int nt = (NTILES - bx + GRIDX - 1) / GRIDX;

    // ---- issue A load (queries, stays resident) + first B tile ----
    const __nv_bfloat16* Qsrc = g_Qbf + (size_t)qg * QGROUP * KP;
    for (int i = tid; i < QGROUP * NCH; i += 256)
        cpa16(A_S + (i / NCH) * (APITCH * 2) + (i % NCH) * 16,
              Qsrc + (size_t)(i / NCH) * KP + (i % NCH) * 8);
    {
        const __nv_bfloat16* src = g_Ebf + (size_t)bx * BN * KP;
        for (int i = tid; i < BN * NCH; i += 256)
            cpa16(B_S + (i / NCH) * (APITCH * 2) + (i % NCH) * 16,
                  src + (size_t)(i / NCH) * KP + (i % NCH) * 8);
    }
    CP_COMMIT();

    // per-thread ldmatrix base offsets (bytes, add k*2 per k-step)
    uint32_t a_off[2], b_off[2];
    #pragma unroll
    for (int mt = 0; mt < 2; mt++) {
        int r = wm * 32 + mt * 16 + (lane & 7) + ((lane >> 3) & 1) * 8;
        a_off[mt] = A_S + (uint32_t)r * (APITCH * 2) + (uint32_t)(lane >> 4) * 16;
    }
    #pragma unroll
    for (int np = 0; np < 2; np++) {
        int r = wn * 32 + np * 16 + (lane & 7) + (lane >> 4) * 8;
        b_off[np] = (uint32_t)r * (APITCH * 2) + (uint32_t)((lane >> 3) & 1) * 16;
    }

    float cv[CAND]; int ci[CAND];
    #pragma unroll
    for (int j = 0; j < CAND; j++) { cv[j] = -1e30f; ci[j] = 0x7fffffff; }

    for (int t = 0; t < nt; t++) {
        // prefetch next B tile into the other buffer
        if (t + 1 < nt) {
            int vt = bx + (t + 1) * GRIDX;
            uint32_t base = B_S + (uint32_t)((t + 1) & 1) * BBYTES;
            const __nv_bfloat16* src = g_Ebf + (size_t)vt * BN * KP;
            for (int i = tid; i < BN * NCH; i += 256)
                cpa16(base + (i / NCH) * (APITCH * 2) + (i % NCH) * 16,
                      src + (size_t)(i / NCH) * KP + (i % NCH) * 8);
            CP_COMMIT();
            CP_WAIT(1);
        } else {
            CP_WAIT(0);
        }
        __syncthreads();

        // ---- compute this tile ----
        uint32_t Bbase = B_S + (uint32_t)(t & 1) * BBYTES;
        float d[2][4][4];
        #pragma unroll
        for (int mt = 0; mt < 2; mt++)
            #pragma unroll
            for (int n = 0; n < 4; n++)
                #pragma unroll
                for (int j = 0; j < 4; j++) d[mt][n][j] = 0.f;

        #pragma unroll 5
        for (int k0 = 0; k0 < KP; k0 += 16) {
            uint32_t a[2][4], b[2][4];
            ldsm_x4(a[0], a_off[0] + k0 * 2);
            ldsm_x4(a[1], a_off[1] + k0 * 2);
            ldsm_x4(b[0], Bbase + b_off[0] + k0 * 2);
            ldsm_x4(b[1], Bbase + b_off[1] + k0 * 2);
            #pragma unroll
            for (int mt = 0; mt < 2; mt++) {
                mma_bf16(d[mt][0], a[mt], b[0][0], b[0][1]);
                mma_bf16(d[mt][1], a[mt], b[0][2], b[0][3]);
                mma_bf16(d[mt][2], a[mt], b[1][0], b[1][1]);
                mma_bf16(d[mt][3], a[mt], b[1][2], b[1][3]);
            }
        }

        // ---- stage D to smem ----
        #pragma unroll
        for (int mt = 0; mt < 2; mt++) {
            int r0 = wm * 32 + mt * 16 + (lane >> 2);
            #pragma unroll
            for (int n = 0; n < 4; n++) {
                int c0 = wn * 32 + n * 8 + (lane & 3) * 2;
                *(float2*)&Ds[r0 * DPITCH + c0]       = make_float2(d[mt][n][0], d[mt][n][1]);
                *(float2*)&Ds[(r0 + 8) * DPITCH + c0] = make_float2(d[mt][n][2], d[mt][n][3]);
            }
        }
        __syncthreads();

        // ---- per-query top-16 scan (one thread per query row) ----
        if (tid < QGROUP) {
            const float* row = Ds + tid * DPITCH;
            int vbase = (bx + t * GRIDX) * BN;
            #pragma unroll 8
            for (int c = 0; c < BN; c++) ins16(row[c], vbase + c, cv, ci);
        }
        __syncthreads();
    }

    if (tid < QGROUP) {
        int q = qg * QGROUP + tid;
        size_t base = ((size_t)q * GRIDX + bx) * CAND;
        #pragma unroll
        for (int j = 0; j < CAND; j++) { g_cv[base + j] = cv[j]; g_ci[base + j] = ci[j]; }
    }
}

// ---------------------------------------------------------------------------
// Kernel 4: global approx top-16 -> exact fp32 rescore -> top-5 out
// ---------------------------------------------------------------------------
__global__ void final_kernel(const float* __restrict__ E, const int* __restrict__ ids,
                             float* __restrict__ out) {
    __shared__ float sv[256][CAND];
    __shared__ int   sn[256][CAND];
    __shared__ float ev[CAND];
    int q = blockIdx.x, tid = threadIdx.x;

    float v[CAND]; int nn[CAND];
    #pragma unroll
    for (int j = 0; j < CAND; j++) { v[j] = -1e30f; nn[j] = 0x7fffffff; }
    size_t base = (size_t)q * GRIDX * CAND;
    for (int i = tid; i < GRIDX * CAND; i += 256) ins16(g_cv[base + i], g_ci[base + i], v, nn);
    #pragma unroll
    for (int j = 0; j < CAND; j++) { sv[tid][j] = v[j]; sn[tid][j] = nn[j]; }
    __syncthreads();
    for (int s = 128; s > 0; s >>= 1) {
        if (tid < s) {
            float ov[CAND]; int on[CAND];
            #pragma unroll
            for (int j = 0; j < CAND; j++) {
                v[j] = sv[tid][j]; nn[j] = sn[tid][j];
                ov[j] = sv[tid + s][j]; on[j] = sn[tid + s][j];
            }
            merge16(v, nn, ov, on);
            #pragma unroll
            for (int j = 0; j < CAND; j++) { sv[tid][j] = v[j]; sn[tid][j] = nn[j]; }
        }
        __syncthreads();
    }
    // exact fp32 rescore of the 16 surviving candidates
    int wid = tid >> 5, lane = tid & 31;
    int qid = ids[q];
    float invq = g_invnorm[qid];
    for (int c = wid; c < CAND; c += 8) {
        int vi = sn[0][c];
        float val = -1e30f;
        if (vi >= 0 && vi < VOCAB) {
            const float* a = E + (size_t)qid * DIM;
            const float* b = E + (size_t)vi * DIM;
            float s = 0.f;
            for (int k = lane; k < DIM; k += 32) s += a[k] * b[k];
            #pragma unroll
            for (int off = 16; off; off >>= 1) s += __shfl_xor_sync(0xffffffffu, s, off);
            val = s * invq * g_invnorm[vi];
        }
        if (lane == 0) ev[c] = val;
    }
    __syncthreads();
    if (tid == 0) {
        bool used[CAND];
        #pragma unroll
        for (int j = 0; j < CAND; j++) used[j] = false;
        for (int j = 0; j < TOPK; j++) {
            int best = -1;
            for (int c = 0; c < CAND; c++) {
                if (used[c]) continue;
                if (best < 0 || better(ev[c], sn[0][c], ev[best], sn[0][best])) best = c;
            }
            used[best] = true;
            out[q * TOPK + j] = ev[best];
            out[NQ * TOPK + q * TOPK + j] = (float)sn[0][best];
        }
    }
}

// ---------------------------------------------------------------------------
extern "C" void kernel_launch(void* const* d_in, const int* in_sizes, int n_in,
                              void* d_out, int out_size) {
    const float* E = (const float*)d_in[0];
    const int* ids = (const int*)d_in[1];
    float* out = (float*)d_out;

    cudaFuncSetAttribute(gemm_topk_kernel, cudaFuncAttributeMaxDynamicSharedMemorySize, SMEM_BYTES);

    prep_kernel<<<VOCAB / 8, 256>>>(E);
    gatherq_kernel<<<NQ / 8, 256>>>(E, ids);
    gemm_topk_kernel<<<dim3(NQG, GRIDX), 256, SMEM_BYTES>>>();
    final_kernel<<<NQ, 256>>>(E, ids, out);
}

// round 16
// speedup vs baseline: 1.4450x; 1.0022x over previous
#include <cuda_runtime.h>
#include <cuda_fp16.h>
#include <cstdint>

#define VOCAB 400000
#define DIM 300
#define KP 304                 // padded K (zeros 300..303), 19 k16-steps
#define NCH (KP / 8)           // 38 x 16B chunks per row
#define NQ 512
#define TOPK 5
#define CAND 16
#define BN 64                  // vocab rows per tile
#define NTILES (VOCAB / BN)    // 6250
#define GRIDX 148
#define QGROUP 128
#define NQG (NQ / QGROUP)      // 4

#define APITCH 312             // smem pitch in f16 elems (624B = 39*16, conflict-free)
#define ABYTES (QGROUP * APITCH * 2)   // 79872
#define BBYTES (BN * APITCH * 2)       // 39936
#define DPITCH 66
#define DBYTES (QGROUP * DPITCH * 4)   // 33792
#define SMEM_BYTES (1024 + ABYTES + 2 * BBYTES + DBYTES)

// ---------------- device scratch (no allocation allowed) -------------------
__device__ float g_invnorm[VOCAB];
__device__ __align__(128) __half g_Ehf[(size_t)VOCAB * KP];   // 243 MB
__device__ __align__(128) __half g_Qhf[NQ * KP];
__device__ float g_cv[(size_t)NQ * GRIDX * CAND];
__device__ int   g_ci[(size_t)NQ * GRIDX * CAND];

// ---------------- PTX helpers ----------------------------------------------
__device__ __forceinline__ uint32_t smem_u32(const void* p) {
    uint32_t a;
    asm("{ .reg .u64 t; cvta.to.shared.u64 t, %1; cvt.u32.u64 %0, t; }" : "=r"(a) : "l"(p));
    return a;
}
__device__ __forceinline__ void cpa16(uint32_t dst, const void* src) {
    asm volatile("cp.async.cg.shared.global [%0], [%1], 16;" :: "r"(dst), "l"(src) : "memory");
}
#define CP_COMMIT() asm volatile("cp.async.commit_group;" ::: "memory")
#define CP_WAIT(n)  asm volatile("cp.async.wait_group %0;" :: "n"(n) : "memory")

__device__ __forceinline__ void ldsm_x4(uint32_t* r, uint32_t addr) {
    asm volatile("ldmatrix.sync.aligned.m8n8.x4.shared.b16 {%0,%1,%2,%3}, [%4];"
                 : "=r"(r[0]), "=r"(r[1]), "=r"(r[2]), "=r"(r[3]) : "r"(addr));
}
// f16 in, f16 accumulate: D(2 regs = 4 halfs) = A*B + D
__device__ __forceinline__ void mma_f16(uint32_t* d, const uint32_t* a, uint32_t b0, uint32_t b1) {
    asm volatile("mma.sync.aligned.m16n8k16.row.col.f16.f16.f16.f16 "
                 "{%0,%1}, {%2,%3,%4,%5}, {%6,%7}, {%0,%1};"
                 : "+r"(d[0]), "+r"(d[1])
                 : "r"(a[0]), "r"(a[1]), "r"(a[2]), "r"(a[3]), "r"(b0), "r"(b1));
}

// ---------------- ordering helpers -----------------------------------------
__device__ __forceinline__ bool better(float av, int an, float bv, int bn) {
    return (av > bv) || (av == bv && an < bn);
}
__device__ __forceinline__ void ins16(float s, int n, float* v, int* nn) {
    if (better(s, n, v[CAND - 1], nn[CAND - 1])) {
        v[CAND - 1] = s; nn[CAND - 1] = n;
        #pragma unroll
        for (int j = CAND - 1; j > 0; j--) {
            if (better(v[j], nn[j], v[j - 1], nn[j - 1])) {
                float tv = v[j]; v[j] = v[j - 1]; v[j - 1] = tv;
                int tn = nn[j]; nn[j] = nn[j - 1]; nn[j - 1] = tn;
            }
        }
    }
}
__device__ __forceinline__ void merge16(float* v, int* nn, const float* ov, const int* on) {
    float rv[CAND]; int rn[CAND]; int a = 0, b = 0;
    #pragma unroll
    for (int j = 0; j < CAND; j++) {
        bool ta = better(v[a], nn[a], ov[b], on[b]);
        rv[j] = ta ? v[a] : ov[b];
        rn[j] = ta ? nn[a] : on[b];
        if (ta) a++; else b++;
    }
    #pragma unroll
    for (int j = 0; j < CAND; j++) { v[j] = rv[j]; nn[j] = rn[j]; }
}

// ---------------------------------------------------------------------------
// noop: shifts ncu's skip-5 target so the GEMM is overall launch #6
// ---------------------------------------------------------------------------
__global__ void noop_kernel() {}

// ---------------------------------------------------------------------------
// Kernel 1: per-row invnorm -> f16 normalized table (KP = 304, zeros at end)
// ---------------------------------------------------------------------------
__global__ void prep_kernel(const float* __restrict__ E) {
    int row = blockIdx.x * (blockDim.x >> 5) + (threadIdx.x >> 5);
    int lane = threadIdx.x & 31;
    if (row >= VOCAB) return;
    const float4* r4 = (const float4*)(E + (size_t)row * DIM);
    float s = 0.f;
    for (int i = lane; i < DIM / 4; i += 32) {
        float4 v = r4[i];
        s += v.x * v.x + v.y * v.y + v.z * v.z + v.w * v.w;
    }
    #pragma unroll
    for (int off = 16; off; off >>= 1) s += __shfl_xor_sync(0xffffffffu, s, off);
    float inv = 1.0f / sqrtf(s);
    if (lane == 0) g_invnorm[row] = inv;
    const float* src = E + (size_t)row * DIM;
    __half2* dst = (__half2*)(g_Ehf + (size_t)row * KP);
    for (int j = lane; j < KP / 2; j += 32) {
        int k = 2 * j;
        float a = (k < DIM) ? src[k] * inv : 0.f;
        float b = (k + 1 < DIM) ? src[k + 1] * inv : 0.f;
        dst[j] = __floats2half2_rn(a, b);
    }
}

// ---------------------------------------------------------------------------
// Kernel 2: gather queries -> f16 normalized, padded
// ---------------------------------------------------------------------------
__global__ void gatherq_kernel(const float* __restrict__ E, const int* __restrict__ ids) {
    int q = blockIdx.x * (blockDim.x >> 5) + (threadIdx.x >> 5);
    int lane = threadIdx.x & 31;
    if (q >= NQ) return;
    int id = ids[q];
    float inv = g_invnorm[id];
    const float* src = E + (size_t)id * DIM;
    __half2* dst = (__half2*)(g_Qhf + (size_t)q * KP);
    for (int j = lane; j < KP / 2; j += 32) {
        int k = 2 * j;
        float a = (k < DIM) ? src[k] * inv : 0.f;
        float b = (k + 1 < DIM) ? src[k + 1] * inv : 0.f;
        dst[j] = __floats2half2_rn(a, b);
    }
}

// ---------------------------------------------------------------------------
// Kernel 3: f16 mma.sync GEMM (128 queries x 64 vocab x K=304) + top-16
// 256 threads = 8 warps (4 in M x 2 in N). Warp tile 32x32. f16 accumulators.
// ---------------------------------------------------------------------------
__global__ __launch_bounds__(256, 1) void gemm_topk_kernel() {
    extern __shared__ char smem[];
    uint32_t sb = smem_u32(smem);
    uint32_t ab = (sb + 1023u) & ~1023u;
    const uint32_t A_S = ab;
    const uint32_t B_S = ab + ABYTES;
    float* Ds = (float*)(smem + (ab - sb) + ABYTES + 2 * BBYTES);

    const int tid = threadIdx.x;
    const int lane = tid & 31;
    const int wid = tid >> 5;
    const int wm = wid & 3;          // 0..3 -> M
    const int wn = wid >> 2;         // 0..1 -> N
    const int qg = blockIdx.x;
    const int bx = blockIdx.y;
    const int nt = (NTILES - bx + GRIDX - 1) / GRIDX;

    // A (resident) + first B tile
    const __half* Qsrc = g_Qhf + (size_t)qg * QGROUP * KP;
    for (int i = tid; i < QGROUP * NCH; i += 256)
        cpa16(A_S + (i / NCH) * (APITCH * 2) + (i % NCH) * 16,
              Qsrc + (size_t)(i / NCH) * KP + (i % NCH) * 8);
    {
        const __half* src = g_Ehf + (size_t)bx * BN * KP;
        for (int i = tid; i < BN * NCH; i += 256)
            cpa16(B_S + (i / NCH) * (APITCH * 2) + (i % NCH) * 16,
                  src + (size_t)(i / NCH) * KP + (i % NCH) * 8);
    }
    CP_COMMIT();

    uint32_t a_off[2], b_off[2];
    #pragma unroll
    for (int mt = 0; mt < 2; mt++) {
        int r = wm * 32 + mt * 16 + (lane & 7) + ((lane >> 3) & 1) * 8;
        a_off[mt] = A_S + (uint32_t)r * (APITCH * 2) + (uint32_t)(lane >> 4) * 16;
    }
    #pragma unroll
    for (int np = 0; np < 2; np++) {
        int r = wn * 32 + np * 16 + (lane & 7) + (lane >> 4) * 8;
        b_off[np] = (uint32_t)r * (APITCH * 2) + (uint32_t)((lane >> 3) & 1) * 16;
    }

    float cv[CAND]; int ci[CAND];
    #pragma unroll
    for (int j = 0; j < CAND; j++) { cv[j] = -1e30f; ci[j] = 0x7fffffff; }

    for (int t = 0; t < nt; t++) {
        if (t + 1 < nt) {
            int vt = bx + (t + 1) * GRIDX;
            uint32_t base = B_S + (uint32_t)((t + 1) & 1) * BBYTES;
            const __half* src = g_Ehf + (size_t)vt * BN * KP;
            for (int i = tid; i < BN * NCH; i += 256)
                cpa16(base + (i / NCH) * (APITCH * 2) + (i % NCH) * 16,
                      src + (size_t)(i / NCH) * KP + (i % NCH) * 8);
            CP_COMMIT();
            CP_WAIT(1);
        } else {
            CP_WAIT(0);
        }
        __syncthreads();

        uint32_t Bbase = B_S + (uint32_t)(t & 1) * BBYTES;
        uint32_t d[2][4][2];
        #pragma unroll
        for (int mt = 0; mt < 2; mt++)
            #pragma unroll
            for (int n = 0; n < 4; n++) { d[mt][n][0] = 0u; d[mt][n][1] = 0u; }

        #pragma unroll 5
        for (int k0 = 0; k0 < KP; k0 += 16) {
            uint32_t a[2][4], b[2][4];
            ldsm_x4(a[0], a_off[0] + k0 * 2);
            ldsm_x4(a[1], a_off[1] + k0 * 2);
            ldsm_x4(b[0], Bbase + b_off[0] + k0 * 2);
            ldsm_x4(b[1], Bbase + b_off[1] + k0 * 2);
            #pragma unroll
            for (int mt = 0; mt < 2; mt++) {
                mma_f16(d[mt][0], a[mt], b[0][0], b[0][1]);
                mma_f16(d[mt][1], a[mt], b[0][2], b[0][3]);
                mma_f16(d[mt][2], a[mt], b[1][0], b[1][1]);
                mma_f16(d[mt][3], a[mt], b[1][2], b[1][3]);
            }
        }

        // stage D (unpack f16x2 -> fp32) to smem
        #pragma unroll
        for (int mt = 0; mt < 2; mt++) {
            int r0 = wm * 32 + mt * 16 + (lane >> 2);
            #pragma unroll
            for (int n = 0; n < 4; n++) {
                int c0 = wn * 32 + n * 8 + (lane & 3) * 2;
                float2 lo = __half22float2(*(__half2*)&d[mt][n][0]);
                float2 hi = __half22float2(*(__half2*)&d[mt][n][1]);
                *(float2*)&Ds[r0 * DPITCH + c0]       = lo;
                *(float2*)&Ds[(r0 + 8) * DPITCH + c0] = hi;
            }
        }
        __syncthreads();

        if (tid < QGROUP) {
            const float* row = Ds + tid * DPITCH;
            int vbase = (bx + t * GRIDX) * BN;
            #pragma unroll 8
            for (int c = 0; c < BN; c++) ins16(row[c], vbase + c, cv, ci);
        }
        __syncthreads();
    }

    if (tid < QGROUP) {
        int q = qg * QGROUP + tid;
        size_t base = ((size_t)q * GRIDX + bx) * CAND;
        #pragma unroll
        for (int j = 0; j < CAND; j++) { g_cv[base + j] = cv[j]; g_ci[base + j] = ci[j]; }
    }
}

// ---------------------------------------------------------------------------
// Kernel 4: global approx top-16 -> exact fp32 rescore -> top-5 out
// ---------------------------------------------------------------------------
__global__ void final_kernel(const float* __restrict__ E, const int* __restrict__ ids,
                             float* __restrict__ out) {
    __shared__ float sv[256][CAND];
    __shared__ int   sn[256][CAND];
    __shared__ float ev[CAND];
    int q = blockIdx.x, tid = threadIdx.x;

    float v[CAND]; int nn[CAND];
    #pragma unroll
    for (int j = 0; j < CAND; j++) { v[j] = -1e30f; nn[j] = 0x7fffffff; }
    size_t base = (size_t)q * GRIDX * CAND;
    for (int i = tid; i < GRIDX * CAND; i += 256) ins16(g_cv[base + i], g_ci[base + i], v, nn);
    #pragma unroll
    for (int j = 0; j < CAND; j++) { sv[tid][j] = v[j]; sn[tid][j] = nn[j]; }
    __syncthreads();
    for (int s = 128; s > 0; s >>= 1) {
        if (tid < s) {
            float ov[CAND]; int on[CAND];
            #pragma unroll
            for (int j = 0; j < CAND; j++) {
                v[j] = sv[tid][j]; nn[j] = sn[tid][j];
                ov[j] = sv[tid + s][j]; on[j] = sn[tid + s][j];
            }
            merge16(v, nn, ov, on);
            #pragma unroll
            for (int j = 0; j < CAND; j++) { sv[tid][j] = v[j]; sn[tid][j] = nn[j]; }
        }
        __syncthreads();
    }
    // exact fp32 rescore of the 16 surviving candidates
    int wid = tid >> 5, lane = tid & 31;
    int qid = ids[q];
    float invq = g_invnorm[qid];
    for (int c = wid; c < CAND; c += 8) {
        int vi = sn[0][c];
        float val = -1e30f;
        if (vi >= 0 && vi < VOCAB) {
            const float* a = E + (size_t)qid * DIM;
            const float* b = E + (size_t)vi * DIM;
            float s = 0.f;
            for (int k = lane; k < DIM; k += 32) s += a[k] * b[k];
            #pragma unroll
            for (int off = 16; off; off >>= 1) s += __shfl_xor_sync(0xffffffffu, s, off);
            val = s * invq * g_invnorm[vi];
        }
        if (lane == 0) ev[c] = val;
    }
    __syncthreads();
    if (tid == 0) {
        bool used[CAND];
        #pragma unroll
        for (int j = 0; j < CAND; j++) used[j] = false;
        for (int j = 0; j < TOPK; j++) {
            int best = -1;
            for (int c = 0; c < CAND; c++) {
                if (used[c]) continue;
                if (best < 0 || better(ev[c], sn[0][c], ev[best], sn[0][best])) best = c;
            }
            used[best] = true;
            out[q * TOPK + j] = ev[best];
            out[NQ * TOPK + q * TOPK + j] = (float)sn[0][best];
        }
    }
}

// ---------------------------------------------------------------------------
extern "C" void kernel_launch(void* const* d_in, const int* in_sizes, int n_in,
                              void* d_out, int out_size) {
    const float* E = (const float*)d_in[0];
    const int* ids = (const int*)d_in[1];
    float* out = (float*)d_out;

    cudaFuncSetAttribute(gemm_topk_kernel, cudaFuncAttributeMaxDynamicSharedMemorySize, SMEM_BYTES);

    prep_kernel<<<VOCAB / 8, 256>>>(E);                         // overall #3
    gatherq_kernel<<<NQ / 8, 256>>>(E, ids);                    // overall #4
    noop_kernel<<<1, 32>>>();                                   // overall #5
    gemm_topk_kernel<<<dim3(NQG, GRIDX), 256, SMEM_BYTES>>>();  // overall #6 <- ncu
    final_kernel<<<NQ, 256>>>(E, ids, out);                     // overall #7
}